// round 2
// baseline (speedup 1.0000x reference)
#include <cuda_runtime.h>
#include <cstdio>

// Problem constants
#define BATCH 2
#define SEQ   2048
#define CDIM  2048
#define NHEAD 16
#define HDIM  128
#define C3    (3*CDIM)          // 6144
#define MROWS (BATCH*SEQ)       // 4096
static __device__ __constant__ float kScale = 0.08838834764831845f; // 1/sqrt(128)

// Scratch (device globals: allocation-free)
__device__ float g_qkv[(size_t)BATCH*SEQ*C3];   // [B,T,3C]  ~100.7 MB
__device__ float g_y  [(size_t)BATCH*SEQ*CDIM]; // [B,T,C]   ~33.5 MB

// ---------------------------------------------------------------------------
// SGEMM: C[M,N] = A[M,K] @ B[K,N], row-major, M%128==0, N%128==0, K%8==0
// 256 threads, 128x128 block tile, 8x8 per-thread tile, KT=8
// ---------------------------------------------------------------------------
__global__ __launch_bounds__(256) void sgemm128(
    const float* __restrict__ A, const float* __restrict__ B,
    float* __restrict__ C, int M, int N, int K)
{
    __shared__ float As[8][128];
    __shared__ float Bs[8][128];

    const int tid = threadIdx.x;
    const int tx  = tid & 15;
    const int ty  = tid >> 4;
    const int m0  = blockIdx.y * 128;
    const int n0  = blockIdx.x * 128;

    // load mapping
    const int arow  = tid >> 1;          // 0..127
    const int acol4 = (tid & 1) * 4;     // 0 or 4
    const int brow  = tid >> 5;          // 0..7
    const int bcol4 = (tid & 31) * 4;    // 0..124

    const float* Aptr = A + (size_t)(m0 + arow) * K + acol4;
    const float* Bptr = B + (size_t)brow * N + n0 + bcol4;

    float acc[8][8];
    #pragma unroll
    for (int i = 0; i < 8; i++)
        #pragma unroll
        for (int j = 0; j < 8; j++) acc[i][j] = 0.f;

    for (int k0 = 0; k0 < K; k0 += 8) {
        float4 av = *(const float4*)(Aptr + k0);
        float4 bv = *(const float4*)(Bptr + (size_t)k0 * N);
        As[acol4 + 0][arow] = av.x;
        As[acol4 + 1][arow] = av.y;
        As[acol4 + 2][arow] = av.z;
        As[acol4 + 3][arow] = av.w;
        *(float4*)&Bs[brow][bcol4] = bv;
        __syncthreads();

        #pragma unroll
        for (int kk = 0; kk < 8; kk++) {
            float a[8], b[8];
            *(float4*)(a)     = *(const float4*)&As[kk][ty * 8];
            *(float4*)(a + 4) = *(const float4*)&As[kk][ty * 8 + 4];
            *(float4*)(b)     = *(const float4*)&Bs[kk][tx * 8];
            *(float4*)(b + 4) = *(const float4*)&Bs[kk][tx * 8 + 4];
            #pragma unroll
            for (int i = 0; i < 8; i++)
                #pragma unroll
                for (int j = 0; j < 8; j++)
                    acc[i][j] = fmaf(a[i], b[j], acc[i][j]);
        }
        __syncthreads();
    }

    #pragma unroll
    for (int i = 0; i < 8; i++) {
        float* out = C + (size_t)(m0 + ty * 8 + i) * N + n0 + tx * 8;
        *(float4*)(out)     = make_float4(acc[i][0], acc[i][1], acc[i][2], acc[i][3]);
        *(float4*)(out + 4) = make_float4(acc[i][4], acc[i][5], acc[i][6], acc[i][7]);
    }
}

// ---------------------------------------------------------------------------
// RoPE (in-place on g_qkv, q and k). Also folds 1/sqrt(d) into q.
// one thread per (b, t, qk, head, d<64) pair
// ---------------------------------------------------------------------------
__global__ __launch_bounds__(256) void rope_kernel(
    float* __restrict__ qkv, const float* __restrict__ cosp,
    const float* __restrict__ sinp)
{
    const int HALF = HDIM / 2; // 64
    int idx = blockIdx.x * blockDim.x + threadIdx.x;
    int d  = idx & (HALF - 1);
    int h  = (idx >> 6) & (NHEAD - 1);
    int qk = (idx >> 10) & 1;
    int t  = (idx >> 11) & (SEQ - 1);
    int b  = idx >> 22;

    float* base = qkv + ((size_t)(b * SEQ + t)) * C3 + qk * CDIM + h * HDIM;
    float x1 = base[d];
    float x2 = base[d + HALF];
    float c1 = cosp[t * HDIM + d];
    float s1 = sinp[t * HDIM + d];
    float c2 = cosp[t * HDIM + d + HALF];
    float s2 = sinp[t * HDIM + d + HALF];
    float o1 = x1 * c1 - x2 * s1;
    float o2 = x2 * c2 + x1 * s2;
    if (qk == 0) { o1 *= kScale; o2 *= kScale; }
    base[d]        = o1;
    base[d + HALF] = o2;
}

// ---------------------------------------------------------------------------
// Flash attention: BM=64 q-rows per block, BN=64 kv-tile, D=128
// grid (SEQ/64, NHEAD, BATCH), 256 threads (16x16), online softmax
// reads q/k/v strided out of g_qkv, writes y in [B,T,C]
// ---------------------------------------------------------------------------
#define BM 64
#define BN 64
// smem floats: Qs[128][68] + Ks[128][68] + Vs[64][128] + Ps[64][65]
#define ATTN_SMEM_FLOATS (128*68 + 128*68 + 64*128 + 64*65)

__global__ __launch_bounds__(256) void attn_kernel(
    const float* __restrict__ qkv, float* __restrict__ y)
{
    extern __shared__ float sm[];
    float* Qs = sm;                    // [128][68] transposed: Qs[d][r]
    float* Ks = Qs + 128 * 68;         // [128][68] transposed: Ks[d][n]
    float* Vs = Ks + 128 * 68;         // [64][128] natural:   Vs[n][d]
    float* Ps = Vs + 64 * 128;         // [64][65]

    const int tid = threadIdx.x;
    const int tx  = tid & 15;
    const int ty  = tid >> 4;
    const int qt  = blockIdx.x;
    const int h   = blockIdx.y;
    const int b   = blockIdx.z;

    const size_t base = ((size_t)b * SEQ) * C3 + (size_t)h * HDIM;
    const float* Qg = qkv + base;          // row stride C3
    const float* Kg = Qg + CDIM;
    const float* Vg = Qg + 2 * CDIM;
    const int t0 = qt * BM;

    // load Q tile transposed
    for (int i = tid; i < BM * 32; i += 256) {
        int r  = i >> 5;
        int d4 = (i & 31) * 4;
        float4 v = *(const float4*)(Qg + (size_t)(t0 + r) * C3 + d4);
        Qs[(d4 + 0) * 68 + r] = v.x;
        Qs[(d4 + 1) * 68 + r] = v.y;
        Qs[(d4 + 2) * 68 + r] = v.z;
        Qs[(d4 + 3) * 68 + r] = v.w;
    }

    float O[4][8];
    float mrow[4], lrow[4];
    #pragma unroll
    for (int i = 0; i < 4; i++) {
        mrow[i] = -1e30f; lrow[i] = 0.f;
        #pragma unroll
        for (int u = 0; u < 8; u++) O[i][u] = 0.f;
    }

    for (int kt = 0; kt < SEQ / BN; kt++) {
        const int s0 = kt * BN;
        __syncthreads(); // all threads done with Ks/Vs/Ps from previous iter
        for (int i = tid; i < BN * 32; i += 256) {
            int r  = i >> 5;
            int d4 = (i & 31) * 4;
            float4 v = *(const float4*)(Kg + (size_t)(s0 + r) * C3 + d4);
            Ks[(d4 + 0) * 68 + r] = v.x;
            Ks[(d4 + 1) * 68 + r] = v.y;
            Ks[(d4 + 2) * 68 + r] = v.z;
            Ks[(d4 + 3) * 68 + r] = v.w;
            float4 w = *(const float4*)(Vg + (size_t)(s0 + r) * C3 + d4);
            *(float4*)&Vs[r * 128 + d4] = w;
        }
        __syncthreads();

        // S[4][4] = Q Kt  (scale pre-folded into q)
        float S[4][4];
        #pragma unroll
        for (int i = 0; i < 4; i++)
            #pragma unroll
            for (int j = 0; j < 4; j++) S[i][j] = 0.f;

        #pragma unroll 4
        for (int d = 0; d < HDIM; d++) {
            float a[4], bb[4];
            *(float4*)a  = *(const float4*)&Qs[d * 68 + ty * 4];
            *(float4*)bb = *(const float4*)&Ks[d * 68 + tx * 4];
            #pragma unroll
            for (int i = 0; i < 4; i++)
                #pragma unroll
                for (int j = 0; j < 4; j++)
                    S[i][j] = fmaf(a[i], bb[j], S[i][j]);
        }

        // online softmax update (row groups of 4 per thread; 16 tx lanes/row)
        #pragma unroll
        for (int i = 0; i < 4; i++) {
            float mx = fmaxf(fmaxf(S[i][0], S[i][1]), fmaxf(S[i][2], S[i][3]));
            #pragma unroll
            for (int off = 8; off > 0; off >>= 1)
                mx = fmaxf(mx, __shfl_xor_sync(0xffffffffu, mx, off));
            float mnew = fmaxf(mrow[i], mx);
            float corr = __expf(mrow[i] - mnew);
            mrow[i] = mnew;
            float rs = 0.f;
            #pragma unroll
            for (int j = 0; j < 4; j++) {
                float p = __expf(S[i][j] - mnew);
                S[i][j] = p;
                rs += p;
            }
            #pragma unroll
            for (int off = 8; off > 0; off >>= 1)
                rs += __shfl_xor_sync(0xffffffffu, rs, off);
            lrow[i] = lrow[i] * corr + rs;
            #pragma unroll
            for (int u = 0; u < 8; u++) O[i][u] *= corr;
            #pragma unroll
            for (int j = 0; j < 4; j++)
                Ps[(ty * 4 + i) * 65 + tx * 4 + j] = S[i][j];
        }
        __syncthreads();

        // O += P @ V
        #pragma unroll 2
        for (int j = 0; j < BN; j++) {
            float p[4];
            #pragma unroll
            for (int i = 0; i < 4; i++) p[i] = Ps[(ty * 4 + i) * 65 + j];
            float v[8];
            *(float4*)(v)     = *(const float4*)&Vs[j * 128 + tx * 8];
            *(float4*)(v + 4) = *(const float4*)&Vs[j * 128 + tx * 8 + 4];
            #pragma unroll
            for (int i = 0; i < 4; i++)
                #pragma unroll
                for (int u = 0; u < 8; u++)
                    O[i][u] = fmaf(p[i], v[u], O[i][u]);
        }
    }

    // epilogue: O/l -> y[b, t, h*128 + c]
    #pragma unroll
    for (int i = 0; i < 4; i++) {
        float inv = 1.f / lrow[i];
        int t = t0 + ty * 4 + i;
        float* out = y + ((size_t)b * SEQ + t) * CDIM + h * HDIM + tx * 8;
        *(float4*)(out)     = make_float4(O[i][0]*inv, O[i][1]*inv, O[i][2]*inv, O[i][3]*inv);
        *(float4*)(out + 4) = make_float4(O[i][4]*inv, O[i][5]*inv, O[i][6]*inv, O[i][7]*inv);
    }
}

// ---------------------------------------------------------------------------
extern "C" void kernel_launch(void* const* d_in, const int* in_sizes, int n_in,
                              void* d_out, int out_size)
{
    const float* x     = (const float*)d_in[0];
    const float* cosp  = (const float*)d_in[1];
    const float* sinp  = (const float*)d_in[2];
    const float* Wqkv  = (const float*)d_in[3];
    const float* Wproj = (const float*)d_in[4];
    float* out = (float*)d_out;

    float *qkv = nullptr, *y = nullptr;
    cudaGetSymbolAddress((void**)&qkv, g_qkv);
    cudaGetSymbolAddress((void**)&y,   g_y);

    const int attn_smem = ATTN_SMEM_FLOATS * 4;
    cudaFuncSetAttribute(attn_kernel, cudaFuncAttributeMaxDynamicSharedMemorySize, attn_smem);

    // 1) qkv = x @ W_qkv
    {
        dim3 grid(C3 / 128, MROWS / 128);
        sgemm128<<<grid, 256>>>(x, Wqkv, qkv, MROWS, C3, CDIM);
    }
    // 2) RoPE in place on q,k (folds 1/sqrt(d) into q)
    {
        int total = BATCH * SEQ * 2 * NHEAD * (HDIM / 2); // 8388608
        rope_kernel<<<total / 256, 256>>>(qkv, cosp, sinp);
    }
    // 3) flash attention -> y [B,T,C]
    {
        dim3 grid(SEQ / BM, NHEAD, BATCH);
        attn_kernel<<<grid, 256, attn_smem>>>(qkv, y);
    }
    // 4) out = y @ W_proj
    {
        dim3 grid(CDIM / 128, MROWS / 128);
        sgemm128<<<grid, 256>>>(y, Wproj, out, MROWS, CDIM, CDIM);
    }
}

// round 4
// speedup vs baseline: 1.7338x; 1.7338x over previous
#include <cuda_runtime.h>
#include <cstdint>

// Problem constants
#define BATCH 2
#define SEQ   2048
#define CDIM  2048
#define NHEAD 16
#define HDIM  128
#define C3    (3*CDIM)          // 6144
#define MROWS (BATCH*SEQ)       // 4096
static __device__ __constant__ float kScale = 0.08838834764831845f; // 1/sqrt(128)

// Scratch (device globals: allocation-free)
__device__ float g_qkv[(size_t)BATCH*SEQ*C3];    // [B,T,3C]
__device__ float g_y  [(size_t)BATCH*SEQ*CDIM];  // [B,T,C] (tf32-rounded by attn)
__device__ float g_xr [(size_t)BATCH*SEQ*CDIM];  // tf32-rounded copy of x
__device__ float g_WtQkv[(size_t)C3*CDIM];       // [3C][C]  W_qkv^T, tf32-rounded
__device__ float g_WtProj[(size_t)CDIM*CDIM];    // [C][C]   W_proj^T, tf32-rounded

// ============================================================================
// helpers
// ============================================================================
__device__ __forceinline__ uint32_t smem_to_u32(const void* p) {
    uint32_t a;
    asm("{ .reg .u64 t; cvta.to.shared.u64 t, %1; cvt.u32.u64 %0, t; }" : "=r"(a) : "l"(p));
    return a;
}
__device__ __forceinline__ float to_tf32(float x) {
    float r;
    asm("cvt.rna.tf32.f32 %0, %1;" : "=f"(r) : "f"(x));
    return r;
}
__device__ __forceinline__ void cp_async16(uint32_t saddr, const void* g) {
    asm volatile("cp.async.cg.shared.global [%0], [%1], 16;" :: "r"(saddr), "l"(g));
}
#define CP_COMMIT() asm volatile("cp.async.commit_group;" ::: "memory")
#define CP_WAIT(n)  asm volatile("cp.async.wait_group %0;" :: "n"(n) : "memory")

__device__ __forceinline__ void mma_tf32(
    float& c0, float& c1, float& c2, float& c3,
    uint32_t a0, uint32_t a1, uint32_t a2, uint32_t a3,
    uint32_t b0, uint32_t b1)
{
    asm volatile(
        "mma.sync.aligned.m16n8k8.row.col.f32.tf32.tf32.f32 "
        "{%0,%1,%2,%3}, {%4,%5,%6,%7}, {%8,%9}, {%0,%1,%2,%3};"
        : "+f"(c0), "+f"(c1), "+f"(c2), "+f"(c3)
        : "r"(a0), "r"(a1), "r"(a2), "r"(a3), "r"(b0), "r"(b1));
}

// ============================================================================
// round fp32 -> tf32 (float4 vectorized)
// ============================================================================
__global__ __launch_bounds__(256) void round_tf32_kernel(
    const float* __restrict__ in, float* __restrict__ out, int n4)
{
    int i = blockIdx.x * blockDim.x + threadIdx.x;
    if (i < n4) {
        float4 v = ((const float4*)in)[i];
        v.x = to_tf32(v.x); v.y = to_tf32(v.y);
        v.z = to_tf32(v.z); v.w = to_tf32(v.w);
        ((float4*)out)[i] = v;
    }
}

// ============================================================================
// Transpose + tf32 round: out[C][R] = tf32(in[R][C])
// ============================================================================
__global__ __launch_bounds__(256) void transpose_k(
    const float* __restrict__ in, float* __restrict__ out, int R, int C)
{
    __shared__ float t[32][33];
    int bx = blockIdx.x * 32, by = blockIdx.y * 32;
    int tx = threadIdx.x, ty = threadIdx.y;
    #pragma unroll
    for (int j = ty; j < 32; j += 8)
        t[j][tx] = in[(size_t)(by + j) * C + bx + tx];
    __syncthreads();
    #pragma unroll
    for (int j = ty; j < 32; j += 8)
        out[(size_t)(bx + j) * R + by + tx] = to_tf32(t[tx][j]);
}

// ============================================================================
// TF32 mma.sync GEMM: C[M,N] = A[M,K] @ Bt[N,K]^T (A, Bt row-major, tf32-pre-rounded)
// 128x128 CTA tile, K chunk 32, cp.async double buffer, 256 threads.
// Warp grid 2(M) x 4(N): warp tile 64x32. m16n8k8 -> 4x4 mma tiles per k-step.
// ============================================================================
#define GK   32
#define LDS_STRIDE 36                              // floats per smem row (pad)
#define TILE_FLOATS (128 * LDS_STRIDE)             // one operand tile
#define BUF_FLOATS  (2 * TILE_FLOATS)              // A + B
#define GSMEM_BYTES (2 * BUF_FLOATS * 4)           // double buffered: 73728 B

__global__ __launch_bounds__(256, 2) void gemm_tf32mma(
    const float* __restrict__ A, const float* __restrict__ Bt,
    float* __restrict__ C, int M, int N, int K)
{
    extern __shared__ float sm[];
    const int tid = threadIdx.x;
    const int wid = tid >> 5;
    const int lid = tid & 31;
    const int wm  = wid & 1;        // 0..1 (M)
    const int wn  = wid >> 1;       // 0..3 (N)
    const int m0  = blockIdx.y * 128;
    const int n0  = blockIdx.x * 128;

    const int lrow = tid >> 3;      // 0..31 -> row/4? no: 256 threads, f covers below
    (void)lrow;

    const uint32_t smem_u32 = smem_to_u32(sm);

    float acc[4][4][4];
    #pragma unroll
    for (int i = 0; i < 4; i++)
        #pragma unroll
        for (int j = 0; j < 4; j++)
            #pragma unroll
            for (int u = 0; u < 4; u++) acc[i][j][u] = 0.f;

    const int nchunk = K / GK;

    // issue cp.async loads for chunk c into buffer s
    auto issue = [&](int c, int s) {
        const float* Ag = A  + (size_t)m0 * K + c * GK;
        const float* Bg = Bt + (size_t)n0 * K + c * GK;
        uint32_t baseA = smem_u32 + (uint32_t)(s * BUF_FLOATS) * 4u;
        uint32_t baseB = baseA + (uint32_t)TILE_FLOATS * 4u;
        #pragma unroll
        for (int i = 0; i < 4; i++) {
            int f   = tid + i * 256;          // 0..1023
            int row = f >> 3;                 // 0..127
            int q   = f & 7;                  // float4 within 32-float row
            uint32_t soff = (uint32_t)(row * LDS_STRIDE + q * 4) * 4u;
            cp_async16(baseA + soff, Ag + (size_t)row * K + q * 4);
            cp_async16(baseB + soff, Bg + (size_t)row * K + q * 4);
        }
    };

    issue(0, 0);
    CP_COMMIT();

    for (int c = 0; c < nchunk; c++) {
        const int s = c & 1;
        if (c + 1 < nchunk) {
            issue(c + 1, s ^ 1);
            CP_COMMIT();
            CP_WAIT(1);
        } else {
            CP_WAIT(0);
        }
        __syncthreads();

        const float* As = sm + s * BUF_FLOATS;
        const float* Bs = As + TILE_FLOATS;
        const int r4 = lid >> 2;   // 0..7
        const int c4 = lid & 3;    // 0..3

        #pragma unroll
        for (int kk = 0; kk < 4; kk++) {
            uint32_t a[4][4], b[4][2];
            #pragma unroll
            for (int mt = 0; mt < 4; mt++) {
                int rb = wm * 64 + mt * 16;
                int kb = kk * 8;
                a[mt][0] = __float_as_uint(As[(rb + r4)     * LDS_STRIDE + kb + c4]);
                a[mt][1] = __float_as_uint(As[(rb + 8 + r4) * LDS_STRIDE + kb + c4]);
                a[mt][2] = __float_as_uint(As[(rb + r4)     * LDS_STRIDE + kb + 4 + c4]);
                a[mt][3] = __float_as_uint(As[(rb + 8 + r4) * LDS_STRIDE + kb + 4 + c4]);
            }
            #pragma unroll
            for (int nt = 0; nt < 4; nt++) {
                int nb = wn * 32 + nt * 8;
                int kb = kk * 8;
                b[nt][0] = __float_as_uint(Bs[(nb + r4) * LDS_STRIDE + kb + c4]);
                b[nt][1] = __float_as_uint(Bs[(nb + r4) * LDS_STRIDE + kb + 4 + c4]);
            }
            #pragma unroll
            for (int mt = 0; mt < 4; mt++)
                #pragma unroll
                for (int nt = 0; nt < 4; nt++)
                    mma_tf32(acc[mt][nt][0], acc[mt][nt][1], acc[mt][nt][2], acc[mt][nt][3],
                             a[mt][0], a[mt][1], a[mt][2], a[mt][3],
                             b[nt][0], b[nt][1]);
        }
        __syncthreads();
    }

    // epilogue: c0,c1 -> (row, col..col+1); c2,c3 -> (row+8, ...)
    const int r4 = lid >> 2;
    const int c2l = 2 * (lid & 3);
    #pragma unroll
    for (int mt = 0; mt < 4; mt++) {
        int row = m0 + wm * 64 + mt * 16 + r4;
        #pragma unroll
        for (int nt = 0; nt < 4; nt++) {
            int col = n0 + wn * 32 + nt * 8 + c2l;
            *(float2*)(C + (size_t)row * N + col) =
                make_float2(acc[mt][nt][0], acc[mt][nt][1]);
            *(float2*)(C + (size_t)(row + 8) * N + col) =
                make_float2(acc[mt][nt][2], acc[mt][nt][3]);
        }
    }
}

// ---------------------------------------------------------------------------
// RoPE (in-place on g_qkv, q and k). Also folds 1/sqrt(d) into q.
// ---------------------------------------------------------------------------
__global__ __launch_bounds__(256) void rope_kernel(
    float* __restrict__ qkv, const float* __restrict__ cosp,
    const float* __restrict__ sinp)
{
    const int HALF = HDIM / 2; // 64
    int idx = blockIdx.x * blockDim.x + threadIdx.x;
    int d  = idx & (HALF - 1);
    int h  = (idx >> 6) & (NHEAD - 1);
    int qk = (idx >> 10) & 1;
    int t  = (idx >> 11) & (SEQ - 1);
    int b  = idx >> 22;

    float* base = qkv + ((size_t)(b * SEQ + t)) * C3 + qk * CDIM + h * HDIM;
    float x1 = base[d];
    float x2 = base[d + HALF];
    float c1 = cosp[t * HDIM + d];
    float s1 = sinp[t * HDIM + d];
    float c2 = cosp[t * HDIM + d + HALF];
    float s2 = sinp[t * HDIM + d + HALF];
    float o1 = x1 * c1 - x2 * s1;
    float o2 = x2 * c2 + x1 * s2;
    if (qk == 0) { o1 *= kScale; o2 *= kScale; }
    base[d]        = o1;
    base[d + HALF] = o2;
}

// ---------------------------------------------------------------------------
// Flash attention: BM=64, BN=64, D=128, fp32 (epilogue rounds y to tf32)
// ---------------------------------------------------------------------------
#define BM 64
#define BN 64
#define ATTN_SMEM_FLOATS (128*68 + 128*68 + 64*128 + 64*65)

__global__ __launch_bounds__(256) void attn_kernel(
    const float* __restrict__ qkv, float* __restrict__ y)
{
    extern __shared__ float smf[];
    float* Qs = smf;                   // [128][68] transposed: Qs[d][r]
    float* Ks = Qs + 128 * 68;         // [128][68] transposed: Ks[d][n]
    float* Vs = Ks + 128 * 68;         // [64][128] natural:   Vs[n][d]
    float* Ps = Vs + 64 * 128;         // [64][65]

    const int tid = threadIdx.x;
    const int tx  = tid & 15;
    const int ty  = tid >> 4;
    const int qt  = blockIdx.x;
    const int h   = blockIdx.y;
    const int b   = blockIdx.z;

    const size_t base = ((size_t)b * SEQ) * C3 + (size_t)h * HDIM;
    const float* Qg = qkv + base;
    const float* Kg = Qg + CDIM;
    const float* Vg = Qg + 2 * CDIM;
    const int t0 = qt * BM;

    for (int i = tid; i < BM * 32; i += 256) {
        int r  = i >> 5;
        int d4 = (i & 31) * 4;
        float4 v = *(const float4*)(Qg + (size_t)(t0 + r) * C3 + d4);
        Qs[(d4 + 0) * 68 + r] = v.x;
        Qs[(d4 + 1) * 68 + r] = v.y;
        Qs[(d4 + 2) * 68 + r] = v.z;
        Qs[(d4 + 3) * 68 + r] = v.w;
    }

    float O[4][8];
    float mrow[4], lrow[4];
    #pragma unroll
    for (int i = 0; i < 4; i++) {
        mrow[i] = -1e30f; lrow[i] = 0.f;
        #pragma unroll
        for (int u = 0; u < 8; u++) O[i][u] = 0.f;
    }

    for (int kt = 0; kt < SEQ / BN; kt++) {
        const int s0 = kt * BN;
        __syncthreads();
        for (int i = tid; i < BN * 32; i += 256) {
            int r  = i >> 5;
            int d4 = (i & 31) * 4;
            float4 v = *(const float4*)(Kg + (size_t)(s0 + r) * C3 + d4);
            Ks[(d4 + 0) * 68 + r] = v.x;
            Ks[(d4 + 1) * 68 + r] = v.y;
            Ks[(d4 + 2) * 68 + r] = v.z;
            Ks[(d4 + 3) * 68 + r] = v.w;
            float4 w = *(const float4*)(Vg + (size_t)(s0 + r) * C3 + d4);
            *(float4*)&Vs[r * 128 + d4] = w;
        }
        __syncthreads();

        float S[4][4];
        #pragma unroll
        for (int i = 0; i < 4; i++)
            #pragma unroll
            for (int j = 0; j < 4; j++) S[i][j] = 0.f;

        #pragma unroll 4
        for (int d = 0; d < HDIM; d++) {
            float a[4], bb[4];
            *(float4*)a  = *(const float4*)&Qs[d * 68 + ty * 4];
            *(float4*)bb = *(const float4*)&Ks[d * 68 + tx * 4];
            #pragma unroll
            for (int i = 0; i < 4; i++)
                #pragma unroll
                for (int j = 0; j < 4; j++)
                    S[i][j] = fmaf(a[i], bb[j], S[i][j]);
        }

        #pragma unroll
        for (int i = 0; i < 4; i++) {
            float mx = fmaxf(fmaxf(S[i][0], S[i][1]), fmaxf(S[i][2], S[i][3]));
            #pragma unroll
            for (int off = 8; off > 0; off >>= 1)
                mx = fmaxf(mx, __shfl_xor_sync(0xffffffffu, mx, off));
            float mnew = fmaxf(mrow[i], mx);
            float corr = __expf(mrow[i] - mnew);
            mrow[i] = mnew;
            float rs = 0.f;
            #pragma unroll
            for (int j = 0; j < 4; j++) {
                float p = __expf(S[i][j] - mnew);
                S[i][j] = p;
                rs += p;
            }
            #pragma unroll
            for (int off = 8; off > 0; off >>= 1)
                rs += __shfl_xor_sync(0xffffffffu, rs, off);
            lrow[i] = lrow[i] * corr + rs;
            #pragma unroll
            for (int u = 0; u < 8; u++) O[i][u] *= corr;
            #pragma unroll
            for (int j = 0; j < 4; j++)
                Ps[(ty * 4 + i) * 65 + tx * 4 + j] = S[i][j];
        }
        __syncthreads();

        #pragma unroll 2
        for (int j = 0; j < BN; j++) {
            float p[4];
            #pragma unroll
            for (int i = 0; i < 4; i++) p[i] = Ps[(ty * 4 + i) * 65 + j];
            float v[8];
            *(float4*)(v)     = *(const float4*)&Vs[j * 128 + tx * 8];
            *(float4*)(v + 4) = *(const float4*)&Vs[j * 128 + tx * 8 + 4];
            #pragma unroll
            for (int i = 0; i < 4; i++)
                #pragma unroll
                for (int u = 0; u < 8; u++)
                    O[i][u] = fmaf(p[i], v[u], O[i][u]);
        }
    }

    // epilogue: tf32(O/l) -> y[b, t, h*128 + c]  (y only feeds the proj GEMM)
    #pragma unroll
    for (int i = 0; i < 4; i++) {
        float inv = 1.f / lrow[i];
        int t = t0 + ty * 4 + i;
        float* out = y + ((size_t)b * SEQ + t) * CDIM + h * HDIM + tx * 8;
        *(float4*)(out) = make_float4(
            to_tf32(O[i][0]*inv), to_tf32(O[i][1]*inv),
            to_tf32(O[i][2]*inv), to_tf32(O[i][3]*inv));
        *(float4*)(out + 4) = make_float4(
            to_tf32(O[i][4]*inv), to_tf32(O[i][5]*inv),
            to_tf32(O[i][6]*inv), to_tf32(O[i][7]*inv));
    }
}

// ---------------------------------------------------------------------------
extern "C" void kernel_launch(void* const* d_in, const int* in_sizes, int n_in,
                              void* d_out, int out_size)
{
    const float* x     = (const float*)d_in[0];
    const float* cosp  = (const float*)d_in[1];
    const float* sinp  = (const float*)d_in[2];
    const float* Wqkv  = (const float*)d_in[3];
    const float* Wproj = (const float*)d_in[4];
    float* out = (float*)d_out;

    float *qkv = nullptr, *y = nullptr, *xr = nullptr, *WtQkv = nullptr, *WtProj = nullptr;
    cudaGetSymbolAddress((void**)&qkv,    g_qkv);
    cudaGetSymbolAddress((void**)&y,      g_y);
    cudaGetSymbolAddress((void**)&xr,     g_xr);
    cudaGetSymbolAddress((void**)&WtQkv,  g_WtQkv);
    cudaGetSymbolAddress((void**)&WtProj, g_WtProj);

    const int attn_smem = ATTN_SMEM_FLOATS * 4;
    cudaFuncSetAttribute(attn_kernel,  cudaFuncAttributeMaxDynamicSharedMemorySize, attn_smem);
    cudaFuncSetAttribute(gemm_tf32mma, cudaFuncAttributeMaxDynamicSharedMemorySize, GSMEM_BYTES);

    // 0) weights: transpose + tf32 round; x: tf32 round into scratch
    transpose_k<<<dim3(C3 / 32,   CDIM / 32), dim3(32, 8)>>>(Wqkv,  WtQkv,  CDIM, C3);
    transpose_k<<<dim3(CDIM / 32, CDIM / 32), dim3(32, 8)>>>(Wproj, WtProj, CDIM, CDIM);
    {
        int n4 = MROWS * CDIM / 4;
        round_tf32_kernel<<<(n4 + 255) / 256, 256>>>(x, xr, n4);
    }

    // 1) qkv = x @ W_qkv   (tf32 mma.sync)
    gemm_tf32mma<<<dim3(C3 / 128, MROWS / 128), 256, GSMEM_BYTES>>>(
        xr, WtQkv, qkv, MROWS, C3, CDIM);

    // 2) RoPE in place on q,k
    {
        int total = BATCH * SEQ * 2 * NHEAD * (HDIM / 2);
        rope_kernel<<<total / 256, 256>>>(qkv, cosp, sinp);
    }

    // 3) flash attention -> y [B,T,C] (tf32-rounded)
    {
        dim3 grid(SEQ / BM, NHEAD, BATCH);
        attn_kernel<<<grid, 256, attn_smem>>>(qkv, y);
    }

    // 4) out = y @ W_proj  (tf32 mma.sync)
    gemm_tf32mma<<<dim3(CDIM / 128, MROWS / 128), 256, GSMEM_BYTES>>>(
        y, WtProj, out, MROWS, CDIM, CDIM);
}

// round 5
// speedup vs baseline: 3.4116x; 1.9677x over previous
#include <cuda_runtime.h>
#include <cstdint>

// Problem constants
#define BATCH 2
#define SEQ   2048
#define CDIM  2048
#define NHEAD 16
#define HDIM  128
#define C3    (3*CDIM)          // 6144
#define MROWS (BATCH*SEQ)       // 4096
static __device__ __constant__ float kScale = 0.08838834764831845f; // 1/sqrt(128)

// Scratch (device globals: allocation-free)
__device__ float g_qkv[(size_t)BATCH*SEQ*C3];    // [B,T,3C]
__device__ float g_y  [(size_t)BATCH*SEQ*CDIM];  // [B,T,C] (tf32-rounded by attn)
__device__ float g_xr [(size_t)BATCH*SEQ*CDIM];  // tf32-rounded copy of x
__device__ float g_WtQkv[(size_t)C3*CDIM];       // [3C][C]  W_qkv^T, tf32-rounded
__device__ float g_WtProj[(size_t)CDIM*CDIM];    // [C][C]   W_proj^T, tf32-rounded

// ============================================================================
// helpers
// ============================================================================
__device__ __forceinline__ uint32_t smem_to_u32(const void* p) {
    uint32_t a;
    asm("{ .reg .u64 t; cvta.to.shared.u64 t, %1; cvt.u32.u64 %0, t; }" : "=r"(a) : "l"(p));
    return a;
}
__device__ __forceinline__ float to_tf32(float x) {
    float r;
    asm("cvt.rna.tf32.f32 %0, %1;" : "=f"(r) : "f"(x));
    return r;
}
__device__ __forceinline__ void cp_async16(uint32_t saddr, const void* g) {
    asm volatile("cp.async.cg.shared.global [%0], [%1], 16;" :: "r"(saddr), "l"(g));
}
#define CP_COMMIT() asm volatile("cp.async.commit_group;" ::: "memory")
#define CP_WAIT(n)  asm volatile("cp.async.wait_group %0;" :: "n"(n) : "memory")

__device__ __forceinline__ void mma_tf32(
    float& c0, float& c1, float& c2, float& c3,
    uint32_t a0, uint32_t a1, uint32_t a2, uint32_t a3,
    uint32_t b0, uint32_t b1)
{
    asm volatile(
        "mma.sync.aligned.m16n8k8.row.col.f32.tf32.tf32.f32 "
        "{%0,%1,%2,%3}, {%4,%5,%6,%7}, {%8,%9}, {%0,%1,%2,%3};"
        : "+f"(c0), "+f"(c1), "+f"(c2), "+f"(c3)
        : "r"(a0), "r"(a1), "r"(a2), "r"(a3), "r"(b0), "r"(b1));
}

// ============================================================================
// round fp32 -> tf32 (float4 vectorized)
// ============================================================================
__global__ __launch_bounds__(256) void round_tf32_kernel(
    const float* __restrict__ in, float* __restrict__ out, int n4)
{
    int i = blockIdx.x * blockDim.x + threadIdx.x;
    if (i < n4) {
        float4 v = ((const float4*)in)[i];
        v.x = to_tf32(v.x); v.y = to_tf32(v.y);
        v.z = to_tf32(v.z); v.w = to_tf32(v.w);
        ((float4*)out)[i] = v;
    }
}

// ============================================================================
// Transpose + tf32 round: out[C][R] = tf32(in[R][C])
// ============================================================================
__global__ __launch_bounds__(256) void transpose_k(
    const float* __restrict__ in, float* __restrict__ out, int R, int C)
{
    __shared__ float t[32][33];
    int bx = blockIdx.x * 32, by = blockIdx.y * 32;
    int tx = threadIdx.x, ty = threadIdx.y;
    #pragma unroll
    for (int j = ty; j < 32; j += 8)
        t[j][tx] = in[(size_t)(by + j) * C + bx + tx];
    __syncthreads();
    #pragma unroll
    for (int j = ty; j < 32; j += 8)
        out[(size_t)(bx + j) * R + by + tx] = to_tf32(t[tx][j]);
}

// ============================================================================
// TF32 mma.sync GEMM: C[M,N] = A[M,K] @ Bt[N,K]^T
// 128x128 CTA tile, K chunk 32, cp.async double buffer, 256 threads.
// ============================================================================
#define GK   32
#define LDS_STRIDE 36
#define TILE_FLOATS (128 * LDS_STRIDE)
#define BUF_FLOATS  (2 * TILE_FLOATS)
#define GSMEM_BYTES (2 * BUF_FLOATS * 4)

__global__ __launch_bounds__(256, 2) void gemm_tf32mma(
    const float* __restrict__ A, const float* __restrict__ Bt,
    float* __restrict__ C, int M, int N, int K)
{
    extern __shared__ float sm[];
    const int tid = threadIdx.x;
    const int wid = tid >> 5;
    const int lid = tid & 31;
    const int wm  = wid & 1;
    const int wn  = wid >> 1;
    const int m0  = blockIdx.y * 128;
    const int n0  = blockIdx.x * 128;

    const uint32_t smem_u32 = smem_to_u32(sm);

    float acc[4][4][4];
    #pragma unroll
    for (int i = 0; i < 4; i++)
        #pragma unroll
        for (int j = 0; j < 4; j++)
            #pragma unroll
            for (int u = 0; u < 4; u++) acc[i][j][u] = 0.f;

    const int nchunk = K / GK;

    auto issue = [&](int c, int s) {
        const float* Ag = A  + (size_t)m0 * K + c * GK;
        const float* Bg = Bt + (size_t)n0 * K + c * GK;
        uint32_t baseA = smem_u32 + (uint32_t)(s * BUF_FLOATS) * 4u;
        uint32_t baseB = baseA + (uint32_t)TILE_FLOATS * 4u;
        #pragma unroll
        for (int i = 0; i < 4; i++) {
            int f   = tid + i * 256;
            int row = f >> 3;
            int q   = f & 7;
            uint32_t soff = (uint32_t)(row * LDS_STRIDE + q * 4) * 4u;
            cp_async16(baseA + soff, Ag + (size_t)row * K + q * 4);
            cp_async16(baseB + soff, Bg + (size_t)row * K + q * 4);
        }
    };

    issue(0, 0);
    CP_COMMIT();

    for (int c = 0; c < nchunk; c++) {
        const int s = c & 1;
        if (c + 1 < nchunk) {
            issue(c + 1, s ^ 1);
            CP_COMMIT();
            CP_WAIT(1);
        } else {
            CP_WAIT(0);
        }
        __syncthreads();

        const float* As = sm + s * BUF_FLOATS;
        const float* Bs = As + TILE_FLOATS;
        const int r4 = lid >> 2;
        const int c4 = lid & 3;

        #pragma unroll
        for (int kk = 0; kk < 4; kk++) {
            uint32_t a[4][4], b[4][2];
            #pragma unroll
            for (int mt = 0; mt < 4; mt++) {
                int rb = wm * 64 + mt * 16;
                int kb = kk * 8;
                a[mt][0] = __float_as_uint(As[(rb + r4)     * LDS_STRIDE + kb + c4]);
                a[mt][1] = __float_as_uint(As[(rb + 8 + r4) * LDS_STRIDE + kb + c4]);
                a[mt][2] = __float_as_uint(As[(rb + r4)     * LDS_STRIDE + kb + 4 + c4]);
                a[mt][3] = __float_as_uint(As[(rb + 8 + r4) * LDS_STRIDE + kb + 4 + c4]);
            }
            #pragma unroll
            for (int nt = 0; nt < 4; nt++) {
                int nb = wn * 32 + nt * 8;
                int kb = kk * 8;
                b[nt][0] = __float_as_uint(Bs[(nb + r4) * LDS_STRIDE + kb + c4]);
                b[nt][1] = __float_as_uint(Bs[(nb + r4) * LDS_STRIDE + kb + 4 + c4]);
            }
            #pragma unroll
            for (int mt = 0; mt < 4; mt++)
                #pragma unroll
                for (int nt = 0; nt < 4; nt++)
                    mma_tf32(acc[mt][nt][0], acc[mt][nt][1], acc[mt][nt][2], acc[mt][nt][3],
                             a[mt][0], a[mt][1], a[mt][2], a[mt][3],
                             b[nt][0], b[nt][1]);
        }
        __syncthreads();
    }

    const int r4 = lid >> 2;
    const int c2l = 2 * (lid & 3);
    #pragma unroll
    for (int mt = 0; mt < 4; mt++) {
        int row = m0 + wm * 64 + mt * 16 + r4;
        #pragma unroll
        for (int nt = 0; nt < 4; nt++) {
            int col = n0 + wn * 32 + nt * 8 + c2l;
            *(float2*)(C + (size_t)row * N + col) =
                make_float2(acc[mt][nt][0], acc[mt][nt][1]);
            *(float2*)(C + (size_t)(row + 8) * N + col) =
                make_float2(acc[mt][nt][2], acc[mt][nt][3]);
        }
    }
}

// ---------------------------------------------------------------------------
// RoPE (in-place on g_qkv, q and k). Folds 1/sqrt(d) into q.
// Rounds q,k to tf32 (they feed the tf32 attention MMAs).
// ---------------------------------------------------------------------------
__global__ __launch_bounds__(256) void rope_kernel(
    float* __restrict__ qkv, const float* __restrict__ cosp,
    const float* __restrict__ sinp)
{
    const int HALF = HDIM / 2; // 64
    int idx = blockIdx.x * blockDim.x + threadIdx.x;
    int d  = idx & (HALF - 1);
    int h  = (idx >> 6) & (NHEAD - 1);
    int qk = (idx >> 10) & 1;
    int t  = (idx >> 11) & (SEQ - 1);
    int b  = idx >> 22;

    float* base = qkv + ((size_t)(b * SEQ + t)) * C3 + qk * CDIM + h * HDIM;
    float x1 = base[d];
    float x2 = base[d + HALF];
    float c1 = cosp[t * HDIM + d];
    float s1 = sinp[t * HDIM + d];
    float c2 = cosp[t * HDIM + d + HALF];
    float s2 = sinp[t * HDIM + d + HALF];
    float o1 = x1 * c1 - x2 * s1;
    float o2 = x2 * c2 + x1 * s2;
    if (qk == 0) { o1 *= kScale; o2 *= kScale; }
    base[d]        = to_tf32(o1);
    base[d + HALF] = to_tf32(o2);
}

// ---------------------------------------------------------------------------
// Flash attention with tf32 mma.sync: BM=128 q rows, BN=64 kv tile, D=128.
// 256 threads = 8 warps, warp w owns rows [w*16, w*16+16).
// S-mma: m16n8k8, A=Qs (row-major), B=Ks (K[n][d] == col-major B). 
// PV-mma: A=Ps, B=Vt (V transposed: Vt[d][kv]).
// ---------------------------------------------------------------------------
#define ABM 128
#define ABN 64
#define QS_STRIDE 132
#define KS_STRIDE 132
#define VS_STRIDE 68
#define PS_STRIDE 68
#define QS_FLOATS (128*QS_STRIDE)
#define KS_FLOATS (64*KS_STRIDE)
#define VT_FLOATS (128*VS_STRIDE)
#define PS_FLOATS (128*PS_STRIDE)
#define ATTN_SMEM_BYTES ((QS_FLOATS + KS_FLOATS + VT_FLOATS + PS_FLOATS) * 4)

__global__ __launch_bounds__(256, 1) void attn_mma_kernel(
    const float* __restrict__ qkv, float* __restrict__ y)
{
    extern __shared__ float sm[];
    float* Qs = sm;                 // [128][132]  Q rows (m) x d (k)
    float* Ks = Qs + QS_FLOATS;     // [64][132]   K rows (n) x d (k)
    float* Vt = Ks + KS_FLOATS;     // [128][68]   d (n) x kv (k), tf32
    float* Ps = Vt + VT_FLOATS;     // [128][68]   q rows (m) x kv (k), tf32

    const int tid = threadIdx.x;
    const int wid = tid >> 5;
    const int lid = tid & 31;
    const int r4  = lid >> 2;       // 0..7
    const int c4  = lid & 3;        // 0..3
    const int h   = blockIdx.y;
    const int b   = blockIdx.z;
    const int t0  = blockIdx.x * ABM;
    const int mrow = wid * 16;      // warp's row offset within tile

    const size_t base = ((size_t)b * SEQ) * C3 + (size_t)h * HDIM;
    const float* Qg = qkv + base;          // row stride C3
    const float* Kg = Qg + CDIM;
    const float* Vg = Qg + 2 * CDIM;

    // load Q tile (stays resident)
    for (int i = tid; i < 128 * 32; i += 256) {
        int r = i >> 5, q = i & 31;
        float4 v = *(const float4*)(Qg + (size_t)(t0 + r) * C3 + q * 4);
        *(float4*)&Qs[r * QS_STRIDE + q * 4] = v;
    }

    float Oa[16][4];
    #pragma unroll
    for (int nt = 0; nt < 16; nt++)
        Oa[nt][0] = Oa[nt][1] = Oa[nt][2] = Oa[nt][3] = 0.f;
    float m0 = -1e30f, m1 = -1e30f, l0 = 0.f, l1 = 0.f;

    for (int kt = 0; kt < SEQ / ABN; kt++) {
        const int s0 = kt * ABN;
        __syncthreads();   // prior iter done with Ks/Vt
        for (int i = tid; i < 64 * 32; i += 256) {
            int r = i >> 5, q = i & 31;
            float4 kv4 = *(const float4*)(Kg + (size_t)(s0 + r) * C3 + q * 4);
            *(float4*)&Ks[r * KS_STRIDE + q * 4] = kv4;
            float4 vv = *(const float4*)(Vg + (size_t)(s0 + r) * C3 + q * 4);
            Vt[(q * 4 + 0) * VS_STRIDE + r] = to_tf32(vv.x);
            Vt[(q * 4 + 1) * VS_STRIDE + r] = to_tf32(vv.y);
            Vt[(q * 4 + 2) * VS_STRIDE + r] = to_tf32(vv.z);
            Vt[(q * 4 + 3) * VS_STRIDE + r] = to_tf32(vv.w);
        }
        __syncthreads();

        // ---- S = Q @ K^T  (warp: 16 rows x 64 cols) ----
        float S[8][4];
        #pragma unroll
        for (int nt = 0; nt < 8; nt++)
            S[nt][0] = S[nt][1] = S[nt][2] = S[nt][3] = 0.f;

        #pragma unroll
        for (int kk = 0; kk < 16; kk++) {
            const int kb = kk * 8;
            uint32_t a0 = __float_as_uint(Qs[(mrow + r4)     * QS_STRIDE + kb + c4]);
            uint32_t a1 = __float_as_uint(Qs[(mrow + 8 + r4) * QS_STRIDE + kb + c4]);
            uint32_t a2 = __float_as_uint(Qs[(mrow + r4)     * QS_STRIDE + kb + 4 + c4]);
            uint32_t a3 = __float_as_uint(Qs[(mrow + 8 + r4) * QS_STRIDE + kb + 4 + c4]);
            #pragma unroll
            for (int nt = 0; nt < 8; nt++) {
                uint32_t b0 = __float_as_uint(Ks[(nt * 8 + r4) * KS_STRIDE + kb + c4]);
                uint32_t b1 = __float_as_uint(Ks[(nt * 8 + r4) * KS_STRIDE + kb + 4 + c4]);
                mma_tf32(S[nt][0], S[nt][1], S[nt][2], S[nt][3],
                         a0, a1, a2, a3, b0, b1);
            }
        }

        // ---- online softmax (row0 = mrow+r4, row1 = +8; 4 lanes per row) ----
        float mx0 = -1e30f, mx1 = -1e30f;
        #pragma unroll
        for (int nt = 0; nt < 8; nt++) {
            mx0 = fmaxf(mx0, fmaxf(S[nt][0], S[nt][1]));
            mx1 = fmaxf(mx1, fmaxf(S[nt][2], S[nt][3]));
        }
        mx0 = fmaxf(mx0, __shfl_xor_sync(0xffffffffu, mx0, 1));
        mx0 = fmaxf(mx0, __shfl_xor_sync(0xffffffffu, mx0, 2));
        mx1 = fmaxf(mx1, __shfl_xor_sync(0xffffffffu, mx1, 1));
        mx1 = fmaxf(mx1, __shfl_xor_sync(0xffffffffu, mx1, 2));

        float mn0 = fmaxf(m0, mx0), mn1 = fmaxf(m1, mx1);
        float cr0 = __expf(m0 - mn0), cr1 = __expf(m1 - mn1);
        m0 = mn0; m1 = mn1;

        float s0s = 0.f, s1s = 0.f;
        #pragma unroll
        for (int nt = 0; nt < 8; nt++) {
            S[nt][0] = __expf(S[nt][0] - mn0);
            S[nt][1] = __expf(S[nt][1] - mn0);
            S[nt][2] = __expf(S[nt][2] - mn1);
            S[nt][3] = __expf(S[nt][3] - mn1);
            s0s += S[nt][0] + S[nt][1];
            s1s += S[nt][2] + S[nt][3];
        }
        s0s += __shfl_xor_sync(0xffffffffu, s0s, 1);
        s0s += __shfl_xor_sync(0xffffffffu, s0s, 2);
        s1s += __shfl_xor_sync(0xffffffffu, s1s, 1);
        s1s += __shfl_xor_sync(0xffffffffu, s1s, 2);
        l0 = l0 * cr0 + s0s;
        l1 = l1 * cr1 + s1s;

        #pragma unroll
        for (int nt = 0; nt < 16; nt++) {
            Oa[nt][0] *= cr0; Oa[nt][1] *= cr0;
            Oa[nt][2] *= cr1; Oa[nt][3] *= cr1;
        }

        // write P (tf32) — only this warp's rows; warp-local visibility suffices
        #pragma unroll
        for (int nt = 0; nt < 8; nt++) {
            Ps[(mrow + r4)     * PS_STRIDE + nt * 8 + 2 * c4]     = to_tf32(S[nt][0]);
            Ps[(mrow + r4)     * PS_STRIDE + nt * 8 + 2 * c4 + 1] = to_tf32(S[nt][1]);
            Ps[(mrow + 8 + r4) * PS_STRIDE + nt * 8 + 2 * c4]     = to_tf32(S[nt][2]);
            Ps[(mrow + 8 + r4) * PS_STRIDE + nt * 8 + 2 * c4 + 1] = to_tf32(S[nt][3]);
        }
        __syncwarp();

        // ---- O += P @ V  (warp: 16 rows x 128 d-cols) ----
        #pragma unroll
        for (int kk = 0; kk < 8; kk++) {
            const int kb = kk * 8;
            uint32_t a0 = __float_as_uint(Ps[(mrow + r4)     * PS_STRIDE + kb + c4]);
            uint32_t a1 = __float_as_uint(Ps[(mrow + 8 + r4) * PS_STRIDE + kb + c4]);
            uint32_t a2 = __float_as_uint(Ps[(mrow + r4)     * PS_STRIDE + kb + 4 + c4]);
            uint32_t a3 = __float_as_uint(Ps[(mrow + 8 + r4) * PS_STRIDE + kb + 4 + c4]);
            #pragma unroll
            for (int nt = 0; nt < 16; nt++) {
                uint32_t b0 = __float_as_uint(Vt[(nt * 8 + r4) * VS_STRIDE + kb + c4]);
                uint32_t b1 = __float_as_uint(Vt[(nt * 8 + r4) * VS_STRIDE + kb + 4 + c4]);
                mma_tf32(Oa[nt][0], Oa[nt][1], Oa[nt][2], Oa[nt][3],
                         a0, a1, a2, a3, b0, b1);
            }
        }
    }

    // epilogue: tf32(O/l) -> y
    float inv0 = 1.f / l0, inv1 = 1.f / l1;
    int row0 = t0 + mrow + r4;
    int row1 = row0 + 8;
    float* y0 = y + ((size_t)b * SEQ + row0) * CDIM + h * HDIM;
    float* y1 = y + ((size_t)b * SEQ + row1) * CDIM + h * HDIM;
    #pragma unroll
    for (int nt = 0; nt < 16; nt++) {
        int col = nt * 8 + 2 * c4;
        *(float2*)(y0 + col) = make_float2(to_tf32(Oa[nt][0] * inv0),
                                           to_tf32(Oa[nt][1] * inv0));
        *(float2*)(y1 + col) = make_float2(to_tf32(Oa[nt][2] * inv1),
                                           to_tf32(Oa[nt][3] * inv1));
    }
}

// ---------------------------------------------------------------------------
extern "C" void kernel_launch(void* const* d_in, const int* in_sizes, int n_in,
                              void* d_out, int out_size)
{
    const float* x     = (const float*)d_in[0];
    const float* cosp  = (const float*)d_in[1];
    const float* sinp  = (const float*)d_in[2];
    const float* Wqkv  = (const float*)d_in[3];
    const float* Wproj = (const float*)d_in[4];
    float* out = (float*)d_out;

    float *qkv = nullptr, *y = nullptr, *xr = nullptr, *WtQkv = nullptr, *WtProj = nullptr;
    cudaGetSymbolAddress((void**)&qkv,    g_qkv);
    cudaGetSymbolAddress((void**)&y,      g_y);
    cudaGetSymbolAddress((void**)&xr,     g_xr);
    cudaGetSymbolAddress((void**)&WtQkv,  g_WtQkv);
    cudaGetSymbolAddress((void**)&WtProj, g_WtProj);

    cudaFuncSetAttribute(attn_mma_kernel, cudaFuncAttributeMaxDynamicSharedMemorySize, ATTN_SMEM_BYTES);
    cudaFuncSetAttribute(gemm_tf32mma,    cudaFuncAttributeMaxDynamicSharedMemorySize, GSMEM_BYTES);

    // 0) weights: transpose + tf32 round; x: tf32 round into scratch
    transpose_k<<<dim3(C3 / 32,   CDIM / 32), dim3(32, 8)>>>(Wqkv,  WtQkv,  CDIM, C3);
    transpose_k<<<dim3(CDIM / 32, CDIM / 32), dim3(32, 8)>>>(Wproj, WtProj, CDIM, CDIM);
    {
        int n4 = MROWS * CDIM / 4;
        round_tf32_kernel<<<(n4 + 255) / 256, 256>>>(x, xr, n4);
    }

    // 1) qkv = x @ W_qkv   (tf32 mma.sync)
    gemm_tf32mma<<<dim3(C3 / 128, MROWS / 128), 256, GSMEM_BYTES>>>(
        xr, WtQkv, qkv, MROWS, C3, CDIM);

    // 2) RoPE in place on q,k (+ tf32 round)
    {
        int total = BATCH * SEQ * 2 * NHEAD * (HDIM / 2);
        rope_kernel<<<total / 256, 256>>>(qkv, cosp, sinp);
    }

    // 3) flash attention (tf32 mma) -> y [B,T,C]
    {
        dim3 grid(SEQ / ABM, NHEAD, BATCH);
        attn_mma_kernel<<<grid, 256, ATTN_SMEM_BYTES>>>(qkv, y);
    }

    // 4) out = y @ W_proj  (tf32 mma.sync)
    gemm_tf32mma<<<dim3(CDIM / 128, MROWS / 128), 256, GSMEM_BYTES>>>(
        y, WtProj, out, MROWS, CDIM, CDIM);
}